// round 3
// baseline (speedup 1.0000x reference)
#include <cuda_runtime.h>
#include <cstdint>

#define B_  64
#define T_  2048
#define IN_ 64
#define H_  256
#define BT  (B_*T_)

#define ALPHA  0.2f
#define OMA    0.8f   // 1 - alpha

// Scratch for P = I @ W_in^T + b, padded by 2 steps so the software-pipelined
// prefetch in rec_kernel never needs a bounds check.
__device__ float g_P[((size_t)BT + 2) * H_];

typedef unsigned long long u64;

__device__ __forceinline__ void ffma2(u64 &acc, u64 a, u64 b) {
    asm("fma.rn.f32x2 %0, %1, %2, %0;" : "+l"(acc) : "l"(a), "l"(b));
}
__device__ __forceinline__ float lo32(u64 v) { return __uint_as_float((unsigned)v); }
__device__ __forceinline__ float hi32(u64 v) { return __uint_as_float((unsigned)(v >> 32)); }

// tanh via MUFU EX2 + MUFU RCP (__fdividef). rel err ~1e-6, far inside the
// 1e-3 budget; avoids the ~15-instr correctly-rounded fp32 divide.
__device__ __forceinline__ float tanh_fast(float x) {
    x = fminf(fmaxf(x, -20.f), 20.f);
    float e = __expf(2.f * x);
    return __fdividef(e - 1.f, e + 1.f);
}

// ---------------------------------------------------------------------------
// Kernel 1: P[bt][h] = sum_k I[bt][k] * W_in[h][k] + b[h]     (FFMA2 version)
// Block = 256 threads (thread = h), 16 (b,t) rows per block.
// W_in row held as 32 packed f32x2 pairs (64 regs); I rows staged in SMEM and
// read as u64 broadcasts.
// ---------------------------------------------------------------------------
__global__ void __launch_bounds__(256) pre_kernel(const float* __restrict__ I,
                                                  const float* __restrict__ Win,
                                                  const float* __restrict__ bvec) {
    __shared__ u64 sI[16 * 32];   // 16 rows x 64 floats (as 32 u64 pairs)
    const int row0 = blockIdx.x * 16;
    const int tid  = threadIdx.x;

    const u64* I2 = (const u64*)(I + (size_t)row0 * IN_);
    sI[tid]       = I2[tid];          // 512 u64 total, 2 per thread, coalesced
    sI[tid + 256] = I2[tid + 256];
    __syncthreads();

    const int h = tid;
    u64 w2[32];
    const u64* W2 = (const u64*)(Win + h * IN_);
#pragma unroll
    for (int j = 0; j < 32; j++) w2[j] = W2[j];
    const float bb = bvec[h];

#pragma unroll 4
    for (int r = 0; r < 16; r++) {
        u64 aA = 0ull, aB = 0ull;
        const u64* ir = &sI[r * 32];
#pragma unroll
        for (int j = 0; j < 16; j++) {
            ffma2(aA, w2[2 * j],     ir[2 * j]);      // broadcast LDS.64
            ffma2(aB, w2[2 * j + 1], ir[2 * j + 1]);
        }
        float acc = (lo32(aA) + hi32(aA)) + (lo32(aB) + hi32(aB)) + bb;
        g_P[(size_t)(row0 + r) * H_ + h] = acc;       // coalesced over h
    }
}

// ---------------------------------------------------------------------------
// Kernel 2: persistent recurrence. grid = 64 CTAs (one per batch), 256 threads
// (one per h). W_rec row h split: k[0,176) in registers as 88 f32x2 pairs,
// k[176,256) in SMEM laid out [chunk][h] (16B/lane stride -> conflict-free
// LDS.128). r broadcast via double-buffered SMEM, ONE __syncthreads per step.
// ---------------------------------------------------------------------------
#define NREG_C  44   // float4-chunks of W in registers  (176 k-cols)
#define NSM_C   20   // float4-chunks of W in SMEM       ( 80 k-cols)

__global__ void __launch_bounds__(256, 1) rec_kernel(const float* __restrict__ x0,
                                                     const float* __restrict__ Wrec,
                                                     float* __restrict__ out_u) {
    extern __shared__ float smem[];
    ulonglong2* wsm = (ulonglong2*)smem;                 // [20][256] = 80 KB
    float* rbuf = smem + NSM_C * H_ * 4;                 // 2 x 256 floats

    const int b = blockIdx.x;
    const int h = threadIdx.x;

    // SMEM part of W: float4 chunks 44..63 of row h -> wsm[c][h]
    const float4* Wrow4 = (const float4*)(Wrec + h * H_);
#pragma unroll
    for (int c = 0; c < NSM_C; c++) {
        float4 v = Wrow4[NREG_C + c];
        wsm[c * H_ + h] = *(ulonglong2*)&v;
    }

    // Register part of W: 88 u64 pairs, split into the two accumulator chains.
    u64 wrA[NREG_C], wrB[NREG_C];
    const u64* Wrow2 = (const u64*)(Wrec + h * H_);
#pragma unroll
    for (int c = 0; c < NREG_C; c++) {
        wrA[c] = Wrow2[2 * c];
        wrB[c] = Wrow2[2 * c + 1];
    }

    float u = x0[b * H_ + h];
    const float* Pb = g_P + (size_t)b * T_ * H_ + h;
    float* ub = out_u + (size_t)b * T_ * H_ + h;

    float pv0 = __ldg(Pb);           // P[t]
    float pv1 = __ldg(Pb + H_);      // P[t+1]  (padded array: always in-bounds)
    __syncthreads();

    for (int t = 0; t < T_; t++) {
        float r = tanh_fast(u);
        float* rb = rbuf + (t & 1) * H_;
        rb[h] = r;
        __syncthreads();

        const ulonglong2* r16 = (const ulonglong2*)rb;
        u64 aA = 0ull, aB = 0ull, aC = 0ull, aD = 0ull;
#pragma unroll
        for (int c = 0; c < NREG_C; c++) {
            ulonglong2 rr = r16[c];              // LDS.128 broadcast
            ffma2(aA, wrA[c], rr.x);
            ffma2(aB, wrB[c], rr.y);
        }
#pragma unroll
        for (int c = 0; c < NSM_C; c++) {
            ulonglong2 rr = r16[NREG_C + c];     // LDS.128 broadcast
            ulonglong2 wv = wsm[c * H_ + h];     // LDS.128 conflict-free
            ffma2(aC, wv.x, rr.x);
            ffma2(aD, wv.y, rr.y);
        }

        float drive = ((lo32(aA) + hi32(aA)) + (lo32(aB) + hi32(aB)))
                    + ((lo32(aC) + hi32(aC)) + (lo32(aD) + hi32(aD))) + pv0;
        u = fmaf(OMA, u, ALPHA * drive);
        ub[(size_t)t * H_] = u;                  // coalesced store

        pv0 = pv1;
        pv1 = __ldg(Pb + (size_t)(t + 2) * H_);  // padded: branchless
    }
}

// ---------------------------------------------------------------------------
// Kernel 3: y[bt][j] = sum_h u[bt][h]*Wout[j][h] + bout[j].  Warp per row.
// ---------------------------------------------------------------------------
__global__ void __launch_bounds__(256) y_kernel(const float* __restrict__ u,
                                                const float* __restrict__ Wout,
                                                const float* __restrict__ bout,
                                                float* __restrict__ y) {
    const int warp = threadIdx.x >> 5;
    const int lane = threadIdx.x & 31;
    const size_t row = (size_t)blockIdx.x * 8 + warp;

    const float4* u4  = (const float4*)(u + row * H_);
    const float4* w04 = (const float4*)(Wout);
    const float4* w14 = (const float4*)(Wout + H_);

    float s0 = 0.f, s1 = 0.f;
#pragma unroll
    for (int j = 0; j < 2; j++) {
        int idx = j * 32 + lane;
        float4 a  = u4[idx];
        float4 w0 = w04[idx];
        float4 w1 = w14[idx];
        s0 += a.x * w0.x + a.y * w0.y + a.z * w0.z + a.w * w0.w;
        s1 += a.x * w1.x + a.y * w1.y + a.z * w1.z + a.w * w1.w;
    }
#pragma unroll
    for (int off = 16; off; off >>= 1) {
        s0 += __shfl_xor_sync(0xffffffffu, s0, off);
        s1 += __shfl_xor_sync(0xffffffffu, s1, off);
    }
    if (lane == 0) {
        y[row * 2 + 0] = s0 + bout[0];
        y[row * 2 + 1] = s1 + bout[1];
    }
}

// ---------------------------------------------------------------------------
// Launch. Inputs (metadata order): x0, I, W_in, W_rec, b, Wout, bout.
// Output: [u (B*T*H) | y (B*T*2)] concatenated.
// ---------------------------------------------------------------------------
extern "C" void kernel_launch(void* const* d_in, const int* in_sizes, int n_in,
                              void* d_out, int out_size) {
    const float* x0   = (const float*)d_in[0];
    const float* I    = (const float*)d_in[1];
    const float* Win  = (const float*)d_in[2];
    const float* Wrec = (const float*)d_in[3];
    const float* bv   = (const float*)d_in[4];
    const float* Wout = (const float*)d_in[5];
    const float* bout = (const float*)d_in[6];

    float* out_u = (float*)d_out;
    float* out_y = out_u + (size_t)BT * H_;

    const int smem_bytes = (NSM_C * H_ * 4 + 2 * H_) * (int)sizeof(float); // 83968
    cudaFuncSetAttribute(rec_kernel, cudaFuncAttributeMaxDynamicSharedMemorySize,
                         smem_bytes);

    pre_kernel<<<BT / 16, 256>>>(I, Win, bv);
    rec_kernel<<<B_, 256, smem_bytes>>>(x0, Wrec, out_u);
    y_kernel<<<BT / 8, 256>>>(out_u, Wout, bout, out_y);
}

// round 9
// speedup vs baseline: 1.0200x; 1.0200x over previous
#include <cuda_runtime.h>
#include <cstdint>

#define B_  64
#define T_  2048
#define IN_ 64
#define H_  256
#define BT  (B_*T_)

#define ALPHA  0.2f
#define OMA    0.8f   // 1 - alpha

// Scratch for P = I @ W_in^T + b, padded by 2 steps for branchless prefetch.
__device__ float g_P[((size_t)BT + 2) * H_];

typedef unsigned long long u64;

__device__ __forceinline__ void ffma2(u64 &acc, u64 a, u64 b) {
    asm("fma.rn.f32x2 %0, %1, %2, %0;" : "+l"(acc) : "l"(a), "l"(b));
}
__device__ __forceinline__ u64 fadd2(u64 a, u64 b) {
    u64 r;
    asm("add.rn.f32x2 %0, %1, %2;" : "=l"(r) : "l"(a), "l"(b));
    return r;
}
__device__ __forceinline__ float lo32(u64 v) { return __uint_as_float((unsigned)v); }
__device__ __forceinline__ float hi32(u64 v) { return __uint_as_float((unsigned)(v >> 32)); }

// tanh via MUFU EX2 + MUFU RCP. rel err ~1e-6, far inside the 1e-3 budget.
__device__ __forceinline__ float tanh_fast(float x) {
    x = fminf(fmaxf(x, -20.f), 20.f);
    float e = __expf(2.f * x);
    return __fdividef(e - 1.f, e + 1.f);
}

// ---------------------------------------------------------------------------
// Kernel 1: P[bt][h] = sum_k I[bt][k] * W_in[h][k] + b[h]
// FIXED: sI now holds the FULL 64-float rows (16 ulonglong2 chunks each);
// compute loop covers all 16 chunks -> k = 0..63.
// Per thread per row: 16 LDS.128 + 32 ffma2.
// ---------------------------------------------------------------------------
__global__ void __launch_bounds__(256) pre_kernel(const float* __restrict__ I,
                                                  const float* __restrict__ Win,
                                                  const float* __restrict__ bvec) {
    __shared__ ulonglong2 sI[16 * 16];  // 16 rows x 64 floats = 256 chunks
    const int row0 = blockIdx.x * 16;
    const int tid  = threadIdx.x;

    {   // stage: 256 x 16B, one chunk per thread, coalesced
        const ulonglong2* I16 = (const ulonglong2*)(I + (size_t)row0 * IN_);
        sI[tid] = I16[tid];
    }
    __syncthreads();

    const int h = tid;
    u64 w2[32];                         // W_in row h: 64 floats as 32 pairs
    const u64* W2 = (const u64*)(Win + h * IN_);
#pragma unroll
    for (int j = 0; j < 32; j++) w2[j] = W2[j];
    const float bb = bvec[h];

#pragma unroll 4
    for (int r = 0; r < 16; r++) {
        u64 aA = 0ull, aB = 0ull;
        const ulonglong2* ir = &sI[r * 16];
#pragma unroll
        for (int j4 = 0; j4 < 16; j4++) {
            ulonglong2 iv = ir[j4];     // I floats 4*j4 .. 4*j4+3 (broadcast)
            ffma2(aA, w2[2 * j4 + 0], iv.x);   // k = 4*j4,   4*j4+1
            ffma2(aB, w2[2 * j4 + 1], iv.y);   // k = 4*j4+2, 4*j4+3
        }
        float acc = (lo32(aA) + hi32(aA)) + (lo32(aB) + hi32(aB)) + bb;
        g_P[(size_t)(row0 + r) * H_ + h] = acc;   // coalesced over h
    }
}

// ---------------------------------------------------------------------------
// Kernel 2: persistent recurrence. grid = 64 CTAs (one per batch), 256 threads
// (one per h). W_rec row h split: k[0,192) in registers (96 u64 pairs, the
// spill-proven R2 footprint), k[192,256) in SMEM [chunk][h] (conflict-free
// LDS.128). r broadcast via double-buffered padded SMEM; 2-deep software
// prefetch on both LDS streams; ONE __syncthreads per step.
// ---------------------------------------------------------------------------
#define NREG_C  48   // float4-chunks of W in registers  (192 k-cols, 192 regs)
#define NSM_C   16   // float4-chunks of W in SMEM       ( 64 k-cols, 64 KB)
#define RPAD    272  // r buffer stride in floats (256 + 16 pad for prefetch)

__global__ void __launch_bounds__(256, 1) rec_kernel(const float* __restrict__ x0,
                                                     const float* __restrict__ Wrec,
                                                     float* __restrict__ out_u) {
    extern __shared__ float smem[];
    ulonglong2* wsm = (ulonglong2*)smem;                 // [16][256] = 64 KB
    float* rbuf = smem + NSM_C * H_ * 4;                 // 2 x RPAD floats

    const int b = blockIdx.x;
    const int h = threadIdx.x;

    // SMEM part of W: float4 chunks 48..63 of row h -> wsm[c][h]
    const float4* Wrow4 = (const float4*)(Wrec + h * H_);
#pragma unroll
    for (int c = 0; c < NSM_C; c++) {
        float4 v = Wrow4[NREG_C + c];
        wsm[c * H_ + h] = *(ulonglong2*)&v;
    }

    // Register part of W: 96 u64 pairs, two accumulator chains.
    u64 wrA[NREG_C], wrB[NREG_C];
    const u64* Wrow2 = (const u64*)(Wrec + h * H_);
#pragma unroll
    for (int c = 0; c < NREG_C; c++) {
        wrA[c] = Wrow2[2 * c];
        wrB[c] = Wrow2[2 * c + 1];
    }

    float u = x0[b * H_ + h];
    const float* Pb = g_P + (size_t)b * T_ * H_ + h;
    float* ub = out_u + (size_t)b * T_ * H_ + h;

    float pv0 = __ldg(Pb);           // P[t]
    float pv1 = __ldg(Pb + H_);      // P[t+1]
    __syncthreads();

    for (int t = 0; t < T_; t++) {
        float r = tanh_fast(u);
        float* rb = rbuf + (t & 1) * RPAD;
        rb[h] = r;
        __syncthreads();

        const ulonglong2* r16 = (const ulonglong2*)rb;   // 64 chunks + pad
        u64 aA = 0ull, aB = 0ull, aC = 0ull, aD = 0ull;

        // 2-deep prefetch pipeline on the r-broadcast stream.
        ulonglong2 p0 = r16[0];
        ulonglong2 p1 = r16[1];
#pragma unroll
        for (int c = 0; c < NREG_C; c++) {
            ulonglong2 cur = p0;
            p0 = p1;
            p1 = r16[c + 2];                     // <= chunk 49: in bounds
            ffma2(aA, wrA[c], cur.x);
            ffma2(aB, wrB[c], cur.y);
        }
        // SMEM-W phase; p0/p1 hold r chunks NREG_C, NREG_C+1 already.
        ulonglong2 q0 = wsm[0 * H_ + h];
        ulonglong2 q1 = wsm[1 * H_ + h];
#pragma unroll
        for (int c = 0; c < NSM_C; c++) {
            ulonglong2 rr = p0;
            p0 = p1;
            p1 = r16[NREG_C + c + 2];            // up to chunk 65: pad covers
            ulonglong2 wv = q0;
            q0 = q1;
            q1 = wsm[((c + 2 < NSM_C) ? (c + 2) : (NSM_C - 1)) * H_ + h];
            ffma2(aC, wv.x, rr.x);
            ffma2(aD, wv.y, rr.y);
        }

        u64 s = fadd2(fadd2(aA, aB), fadd2(aC, aD));
        float drive = (lo32(s) + hi32(s)) + pv0;
        u = fmaf(OMA, u, ALPHA * drive);
        ub[(size_t)t * H_] = u;                  // coalesced store

        pv0 = pv1;
        pv1 = __ldg(Pb + (size_t)(t + 2) * H_);  // padded: branchless
    }
}

// ---------------------------------------------------------------------------
// Kernel 3: y[bt][j] = sum_h u[bt][h]*Wout[j][h] + bout[j].  Warp per row.
// ---------------------------------------------------------------------------
__global__ void __launch_bounds__(256) y_kernel(const float* __restrict__ u,
                                                const float* __restrict__ Wout,
                                                const float* __restrict__ bout,
                                                float* __restrict__ y) {
    const int warp = threadIdx.x >> 5;
    const int lane = threadIdx.x & 31;
    const size_t row = (size_t)blockIdx.x * 8 + warp;

    const float4* u4  = (const float4*)(u + row * H_);
    const float4* w04 = (const float4*)(Wout);
    const float4* w14 = (const float4*)(Wout + H_);

    float s0 = 0.f, s1 = 0.f;
#pragma unroll
    for (int j = 0; j < 2; j++) {
        int idx = j * 32 + lane;
        float4 a  = u4[idx];
        float4 w0 = w04[idx];
        float4 w1 = w14[idx];
        s0 += a.x * w0.x + a.y * w0.y + a.z * w0.z + a.w * w0.w;
        s1 += a.x * w1.x + a.y * w1.y + a.z * w1.z + a.w * w1.w;
    }
#pragma unroll
    for (int off = 16; off; off >>= 1) {
        s0 += __shfl_xor_sync(0xffffffffu, s0, off);
        s1 += __shfl_xor_sync(0xffffffffu, s1, off);
    }
    if (lane == 0) {
        y[row * 2 + 0] = s0 + bout[0];
        y[row * 2 + 1] = s1 + bout[1];
    }
}

// ---------------------------------------------------------------------------
// Launch. Inputs: x0, I, W_in, W_rec, b, Wout, bout.
// Output: [u (B*T*H) | y (B*T*2)] concatenated.
// ---------------------------------------------------------------------------
extern "C" void kernel_launch(void* const* d_in, const int* in_sizes, int n_in,
                              void* d_out, int out_size) {
    const float* x0   = (const float*)d_in[0];
    const float* I    = (const float*)d_in[1];
    const float* Win  = (const float*)d_in[2];
    const float* Wrec = (const float*)d_in[3];
    const float* bv   = (const float*)d_in[4];
    const float* Wout = (const float*)d_in[5];
    const float* bout = (const float*)d_in[6];

    float* out_u = (float*)d_out;
    float* out_y = out_u + (size_t)BT * H_;

    const int smem_bytes = NSM_C * H_ * 16 + 2 * RPAD * 4;   // 65536 + 2176
    cudaFuncSetAttribute(rec_kernel, cudaFuncAttributeMaxDynamicSharedMemorySize,
                         smem_bytes);

    pre_kernel<<<BT / 16, 256>>>(I, Win, bv);
    rec_kernel<<<B_, 256, smem_bytes>>>(x0, Wrec, out_u);
    y_kernel<<<BT / 8, 256>>>(out_u, Wout, bout, out_y);
}